// round 11
// baseline (speedup 1.0000x reference)
#include <cuda_runtime.h>
#include <cuda_fp16.h>
#include <math.h>

#define BB 16
#define CC 384
#define HH 96
#define WW 96
#define HW (HH*WW)
#define CAND 2048
#define ANCH 512
#define KK2 49
#define TAU_INV 10.0f

// ---------------- scratch (device globals; no allocation anywhere) ----------------
__device__ __half g_tn[(size_t)BB*HW*CC];     // teacher, normalized, channels-last, fp16
__device__ __half g_sn[(size_t)BB*HW*CC];     // student,  normalized, channels-last, fp16
__device__ float g_sims[(size_t)BB*CAND*KK2]; // teacher sims (already /TAU), by ORIGINAL id
__device__ float g_ent[BB*CAND];              // by ORIGINAL id
__device__ int   g_order[CAND];               // candidate ids, Morton-sorted
__device__ int   g_sel[BB*ANCH];              // selected ids, Morton-sorted per batch
__device__ float g_loss;

// pixel offsets dy*WW+dx, row-major 7x7, padded to 52 with 0 (center: L1-resident)
__constant__ int c_doff[52] = {
 -291,-290,-289,-288,-287,-286,-285,
 -195,-194,-193,-192,-191,-190,-189,
  -99, -98, -97, -96, -95, -94, -93,
   -3,  -2,  -1,   0,   1,   2,   3,
   93,  94,  95,  96,  97,  98,  99,
  189, 190, 191, 192, 193, 194, 195,
  285, 286, 287, 288, 289, 290, 291,
    0,   0,   0 };

__device__ __forceinline__ unsigned morton7(int y, int x) {
    unsigned m = 0;
#pragma unroll
    for (int i = 0; i < 7; i++)
        m |= (((unsigned)(y >> i) & 1u) << (2 * i + 1)) | (((unsigned)(x >> i) & 1u) << (2 * i));
    return m;
}

// ---------------- k0: zero the loss accumulator ----------------
__global__ void k_zero() { g_loss = 0.0f; }

// ---------------- k_sort: Morton-sort the 2048 candidate ids ----------------
__global__ void __launch_bounds__(1024) k_sort(const int* __restrict__ anchors) {
    __shared__ unsigned key[CAND];
    __shared__ int      id[CAND];
    int t = threadIdx.x;
#pragma unroll
    for (int h = 0; h < 2; h++) {
        int m = t + h * 1024;
        key[m] = morton7(anchors[2 * m], anchors[2 * m + 1]);
        id[m]  = m;
    }
    __syncthreads();
    for (int kk = 2; kk <= CAND; kk <<= 1) {
        for (int j = kk >> 1; j > 0; j >>= 1) {
            int i  = ((t & ~(j - 1)) << 1) | (t & (j - 1));
            int p2 = i | j;
            bool up = ((i & kk) == 0);
            unsigned ki = key[i], kp = key[p2];
            if ((ki > kp) == up) {
                key[i] = kp; key[p2] = ki;
                int ti = id[i]; id[i] = id[p2]; id[p2] = ti;
            }
            __syncthreads();
        }
    }
    g_order[t] = id[t];
    g_order[t + 1024] = id[t + 1024];
}

// ---------------- k1: fused per-pixel L2-normalize + transpose + fp16 cast --------
// One launch, both tensors. Read path: thread = (channel-row cr 0..31, float4
// pixel p4 0..7) -> 12 LDG.128 per thread, all independent (deep MLP, 4x bytes
// per request vs scalar loads).
#define PIX 32
__global__ void __launch_bounds__(256) k_norm_transpose(const float* __restrict__ teacher,
                                                        const float* __restrict__ student) {
    __shared__ float tile[CC][PIX + 1];
    __shared__ float ssum[32][PIX + 1];
    __shared__ float rinv[PIX];
    const int blocks_per_tensor = BB * HW / PIX;      // 4608
    int blk  = blockIdx.x;
    bool is_student = (blk >= blocks_per_tensor);
    if (is_student) blk -= blocks_per_tensor;
    const float* in = is_student ? student : teacher;
    __half* gout    = is_student ? g_sn : g_tn;

    int b    = blk / (HW / PIX);
    int pix0 = (blk % (HW / PIX)) * PIX;
    int t    = threadIdx.x;
    int p4   = t & 7;                        // float4 pixel index (0..7)
    int cr   = t >> 3;                       // channel row group (0..31)
    const float* src = in + (size_t)b * CC * HW + pix0;
    float a0 = 0.f, a1 = 0.f, a2 = 0.f, a3 = 0.f;
#pragma unroll
    for (int i = 0; i < CC / 32; i++) {      // 12 iters, LDG.128, fully coalesced
        int c = i * 32 + cr;
        float4 v = *(const float4*)(src + (size_t)c * HW + p4 * 4);
        tile[c][p4 * 4 + 0] = v.x;
        tile[c][p4 * 4 + 1] = v.y;
        tile[c][p4 * 4 + 2] = v.z;
        tile[c][p4 * 4 + 3] = v.w;
        a0 = fmaf(v.x, v.x, a0);
        a1 = fmaf(v.y, v.y, a1);
        a2 = fmaf(v.z, v.z, a2);
        a3 = fmaf(v.w, v.w, a3);
    }
    ssum[cr][p4 * 4 + 0] = a0;
    ssum[cr][p4 * 4 + 1] = a1;
    ssum[cr][p4 * 4 + 2] = a2;
    ssum[cr][p4 * 4 + 3] = a3;
    __syncthreads();
    if (t < PIX) {                           // one warp: reduce 32 partials/pixel
        float s = 0.0f;
#pragma unroll
        for (int r = 0; r < 32; r++) s += ssum[r][t];
        rinv[t] = 1.0f / fmaxf(sqrtf(s), 1e-12f);
    }
    __syncthreads();
    int lane = t & 31, w = t >> 5;           // 8 warps, 4 pixels each
    __half2* dst = (__half2*)(gout + ((size_t)b * HW + pix0) * CC);
#pragma unroll
    for (int j = 0; j < PIX / 8; j++) {      // 4 pixels per warp
        int pp = w * (PIX / 8) + j;
        float r = rinv[pp];
#pragma unroll
        for (int i2 = 0; i2 < CC / 64; i2++) {  // 6, 128B coalesced half2 stores
            int h2i = lane + 32 * i2;            // half2 index 0..191
            int c = 2 * h2i;
            dst[(size_t)pp * (CC / 2) + h2i] =
                __floats2half2_rn(tile[c][pp] * r, tile[c + 1][pp] * r);
        }
    }
}

// ---------------- distributed window sims (fp16, fp32 accumulate) ----------------
// Warp layout: lane = 8*g + l. Group g owns offsets o = g*13+j. Lane l covers
// channel-chunks {l+8i} (uint4 = 8 halves). Neighbor loads split into 7+6
// half-batches: peak live buffer 28 regs (vs 52), preserving ~7-deep MLP while
// fitting 3 blocks/SM at 256 threads.
__device__ __forceinline__ void window_sims13(const __half* __restrict__ feat,
                                              int b, int y, int x,
                                              int g, int l, float s[13]) {
    const uint4* cp = ((const uint4*)(feat + (size_t)b * HW * CC))
                    + (size_t)(y * WW + x) * (CC / 8);
#pragma unroll
    for (int j = 0; j < 13; j++) s[j] = 0.0f;
#pragma unroll
    for (int i = 0; i < 6; i++) {
        int ci = l + 8 * i;
        uint4 cv = cp[ci];
        __half2 c0 = *(__half2*)&cv.x, c1 = *(__half2*)&cv.y;
        __half2 c2 = *(__half2*)&cv.z, c3 = *(__half2*)&cv.w;
        {
            uint4 n[7];
#pragma unroll
            for (int j = 0; j < 7; j++)
                n[j] = cp[ci + c_doff[g * 13 + j] * (CC / 8)];
#pragma unroll
            for (int j = 0; j < 7; j++) {
                __half2 a = __hmul2(c0, *(__half2*)&n[j].x);
                a = __hfma2(c1, *(__half2*)&n[j].y, a);
                a = __hfma2(c2, *(__half2*)&n[j].z, a);
                a = __hfma2(c3, *(__half2*)&n[j].w, a);
                float2 f = __half22float2(a);
                s[j] += f.x + f.y;
            }
        }
        {
            uint4 n[6];
#pragma unroll
            for (int j = 0; j < 6; j++)
                n[j] = cp[ci + c_doff[g * 13 + 7 + j] * (CC / 8)];
#pragma unroll
            for (int j = 0; j < 6; j++) {
                __half2 a = __hmul2(c0, *(__half2*)&n[j].x);
                a = __hfma2(c1, *(__half2*)&n[j].y, a);
                a = __hfma2(c2, *(__half2*)&n[j].z, a);
                a = __hfma2(c3, *(__half2*)&n[j].w, a);
                float2 f = __half22float2(a);
                s[7 + j] += f.x + f.y;
            }
        }
    }
#pragma unroll
    for (int j = 0; j < 13; j++) {
        float v = s[j];
        v += __shfl_xor_sync(0xffffffffu, v, 1);
        v += __shfl_xor_sync(0xffffffffu, v, 2);
        v += __shfl_xor_sync(0xffffffffu, v, 4);
        s[j] = v * TAU_INV;
    }
}

// ---------------- k2: candidate sims (stored) + entropy, Morton-ordered ----------
__global__ void __launch_bounds__(256, 3) k_cand(const int* __restrict__ anchors) {
    int gw   = (blockIdx.x * blockDim.x + threadIdx.x) >> 5;
    int lane = threadIdx.x & 31;
    if (gw >= BB * CAND) return;
    int b = gw >> 11;                  // / CAND
    int m = g_order[gw & (CAND - 1)];  // Morton-sorted processing order
    int y = anchors[2 * m], x = anchors[2 * m + 1];
    int g = lane >> 3, l = lane & 7;
    bool lead = (l == 0);

    float s[13];
    window_sims13(g_tn, b, y, x, g, l, s);

    // store sims row by ORIGINAL id (group leaders)
    float* srow = g_sims + ((size_t)(b << 11) + m) * KK2;
    if (lead) {
#pragma unroll
        for (int j = 0; j < 13; j++) {
            int o = g * 13 + j;
            if (o < KK2) srow[o] = s[j];
        }
    }

    // distributed entropy of softmax(s)
    float mx = -1e30f;
#pragma unroll
    for (int j = 0; j < 13; j++) {
        int o = g * 13 + j;
        if (o < KK2) mx = fmaxf(mx, s[j]);
    }
#pragma unroll
    for (int off = 16; off; off >>= 1) mx = fmaxf(mx, __shfl_xor_sync(0xffffffffu, mx, off));

    float S = 0.0f;
#pragma unroll
    for (int j = 0; j < 13; j++) {
        int o = g * 13 + j;
        if (lead && o < KK2) S += __expf(s[j] - mx);
    }
#pragma unroll
    for (int off = 16; off; off >>= 1) S += __shfl_xor_sync(0xffffffffu, S, off);
    float rS = 1.0f / S;

    float tacc = 0.0f;
#pragma unroll
    for (int j = 0; j < 13; j++) {
        int o = g * 13 + j;
        if (lead && o < KK2) {
            float p = __expf(s[j] - mx) * rS;
            tacc += p * __logf(p + 1e-6f);
        }
    }
#pragma unroll
    for (int off = 16; off; off >>= 1) tacc += __shfl_xor_sync(0xffffffffu, tacc, off);

    if (lane == 0) g_ent[(b << 11) | m] = -tacc;
}

// ---------------- k3: exact top-512 per batch + Morton re-sort of selection ------
__global__ void __launch_bounds__(1024) k_topk(const int* __restrict__ anchors) {
    __shared__ float v[CAND];
    __shared__ int   idx[CAND];
    __shared__ unsigned mk[ANCH];
    __shared__ int      mi[ANCH];
    int b = blockIdx.x;
    int t = threadIdx.x;   // 1024
    v[t]          = g_ent[b * CAND + t];
    v[t + 1024]   = g_ent[b * CAND + t + 1024];
    idx[t]        = t;
    idx[t + 1024] = t + 1024;
    __syncthreads();
    for (int kk = 2; kk <= CAND; kk <<= 1) {
        for (int j = kk >> 1; j > 0; j >>= 1) {
            int i  = ((t & ~(j - 1)) << 1) | (t & (j - 1));
            int p2 = i | j;
            bool up = ((i & kk) == 0);
            float vi = v[i], vp = v[p2];
            if ((vi > vp) == up) {
                v[i] = vp; v[p2] = vi;
                int ti = idx[i]; idx[i] = idx[p2]; idx[p2] = ti;
            }
            __syncthreads();
        }
    }
    // first 512 = smallest entropies; re-sort them by Morton code for k_kl locality
    if (t < ANCH) {
        int id = idx[t];
        mi[t] = id;
        mk[t] = morton7(anchors[2 * id], anchors[2 * id + 1]);
    }
    __syncthreads();
    for (int kk = 2; kk <= ANCH; kk <<= 1) {
        for (int j = kk >> 1; j > 0; j >>= 1) {
            if (t < ANCH / 2) {
                int i  = ((t & ~(j - 1)) << 1) | (t & (j - 1));
                int p2 = i | j;
                bool up = ((i & kk) == 0);
                unsigned ki = mk[i], kp = mk[p2];
                if ((ki > kp) == up) {
                    mk[i] = kp; mk[p2] = ki;
                    int ti = mi[i]; mi[i] = mi[p2]; mi[p2] = ti;
                }
            }
            __syncthreads();
        }
    }
    if (t < ANCH) g_sel[b * ANCH + t] = mi[t];
}

// ---------------- k4: KL divergence over selected anchors (Morton-ordered) -------
__global__ void __launch_bounds__(256, 3) k_kl(const int* __restrict__ anchors) {
    int gw   = (blockIdx.x * blockDim.x + threadIdx.x) >> 5;
    int lane = threadIdx.x & 31;
    if (gw >= BB * ANCH) return;
    int b = gw >> 9;             // / ANCH
    int m = g_sel[gw];
    int y = anchors[2 * m], x = anchors[2 * m + 1];
    int g = lane >> 3, l = lane & 7;
    bool lead = (l == 0);

    float ss[13];
    window_sims13(g_sn, b, y, x, g, l, ss);

    const float* trow = g_sims + ((size_t)(b << 11) + m) * KK2;
    float st[13];
#pragma unroll
    for (int j = 0; j < 13; j++) {
        int o = g * 13 + j;
        st[j] = (o < KK2) ? trow[o] : -1e30f;   // group-broadcast loads
    }

    float mxs = -1e30f, mxt = -1e30f;
#pragma unroll
    for (int j = 0; j < 13; j++) {
        int o = g * 13 + j;
        if (o < KK2) mxs = fmaxf(mxs, ss[j]);
        mxt = fmaxf(mxt, st[j]);                // invalid slots are -1e30
    }
#pragma unroll
    for (int off = 16; off; off >>= 1) {
        mxs = fmaxf(mxs, __shfl_xor_sync(0xffffffffu, mxs, off));
        mxt = fmaxf(mxt, __shfl_xor_sync(0xffffffffu, mxt, off));
    }

    float Ss = 0.0f, St = 0.0f;
#pragma unroll
    for (int j = 0; j < 13; j++) {
        int o = g * 13 + j;
        if (lead && o < KK2) {
            Ss += __expf(ss[j] - mxs);
            St += __expf(st[j] - mxt);
        }
    }
#pragma unroll
    for (int off = 16; off; off >>= 1) {
        Ss += __shfl_xor_sync(0xffffffffu, Ss, off);
        St += __shfl_xor_sync(0xffffffffu, St, off);
    }
    float ls = __logf(Ss), lt = __logf(St);
    float rSt = 1.0f / St;

    float kacc = 0.0f;
#pragma unroll
    for (int j = 0; j < 13; j++) {
        int o = g * 13 + j;
        if (lead && o < KK2) {
            float dt = st[j] - mxt - lt;
            float ds = ss[j] - mxs - ls;
            kacc += __expf(st[j] - mxt) * (dt - ds);
        }
    }
#pragma unroll
    for (int off = 16; off; off >>= 1) kacc += __shfl_xor_sync(0xffffffffu, kacc, off);

    if (lane == 0) atomicAdd(&g_loss, kacc * rSt);
}

// ---------------- k5: finalize ----------------
__global__ void k_final(float* __restrict__ out) {
    out[0] = g_loss / (float)(BB * ANCH);
}

// ---------------- launch: kernel launches ONLY (graph-capture safe) ----------------
extern "C" void kernel_launch(void* const* d_in, const int* in_sizes, int n_in,
                              void* d_out, int out_size) {
    const float* student = (const float*)d_in[0];
    const float* teacher = (const float*)d_in[1];
    const int*   anchors = (const int*)d_in[2];
    float* out = (float*)d_out;

    k_zero<<<1, 1>>>();
    k_sort<<<1, 1024>>>(anchors);

    int nt_blocks = 2 * BB * HW / PIX;              // 9216 (both tensors, one launch)
    k_norm_transpose<<<nt_blocks, 256>>>(teacher, student);

    int cand_blocks = BB * CAND / 8;                // 4096 blocks, 8 warps each
    k_cand<<<cand_blocks, 256>>>(anchors);

    k_topk<<<BB, 1024>>>(anchors);

    int kl_blocks = BB * ANCH / 8;                  // 1024 blocks
    k_kl<<<kl_blocks, 256>>>(anchors);

    k_final<<<1, 1>>>(out);
}

// round 12
// speedup vs baseline: 1.0339x; 1.0339x over previous
#include <cuda_runtime.h>
#include <cuda_fp16.h>
#include <math.h>

#define BB 16
#define CC 384
#define HH 96
#define WW 96
#define HW (HH*WW)
#define CAND 2048
#define ANCH 512
#define KK2 49
#define TAU_INV 10.0f

// ---------------- scratch (device globals; no allocation anywhere) ----------------
__device__ __half g_tn[(size_t)BB*HW*CC];     // teacher, normalized, channels-last, fp16
__device__ __half g_sn[(size_t)BB*HW*CC];     // student,  normalized, channels-last, fp16
__device__ float g_sims[(size_t)BB*CAND*KK2]; // teacher sims (already /TAU), by ORIGINAL id
__device__ float g_ent[BB*CAND];              // by ORIGINAL id
__device__ int   g_order[CAND];               // candidate ids, Morton-sorted
__device__ int   g_sel[BB*ANCH];              // selected ids, Morton-sorted per batch
__device__ float g_loss;

// pixel offsets dy*WW+dx, row-major 7x7, padded to 52 with 0 (center: L1-resident)
__constant__ int c_doff[52] = {
 -291,-290,-289,-288,-287,-286,-285,
 -195,-194,-193,-192,-191,-190,-189,
  -99, -98, -97, -96, -95, -94, -93,
   -3,  -2,  -1,   0,   1,   2,   3,
   93,  94,  95,  96,  97,  98,  99,
  189, 190, 191, 192, 193, 194, 195,
  285, 286, 287, 288, 289, 290, 291,
    0,   0,   0 };

__device__ __forceinline__ unsigned morton7(int y, int x) {
    unsigned m = 0;
#pragma unroll
    for (int i = 0; i < 7; i++)
        m |= (((unsigned)(y >> i) & 1u) << (2 * i + 1)) | (((unsigned)(x >> i) & 1u) << (2 * i));
    return m;
}

// ---------------- k_sort: Morton-sort candidate ids (+ zero the loss) -------------
__global__ void __launch_bounds__(1024) k_sort(const int* __restrict__ anchors) {
    __shared__ unsigned key[CAND];
    __shared__ int      id[CAND];
    int t = threadIdx.x;
    if (t == 0) g_loss = 0.0f;
#pragma unroll
    for (int h = 0; h < 2; h++) {
        int m = t + h * 1024;
        key[m] = morton7(anchors[2 * m], anchors[2 * m + 1]);
        id[m]  = m;
    }
    __syncthreads();
    for (int kk = 2; kk <= CAND; kk <<= 1) {
        for (int j = kk >> 1; j > 0; j >>= 1) {
            int i  = ((t & ~(j - 1)) << 1) | (t & (j - 1));
            int p2 = i | j;
            bool up = ((i & kk) == 0);
            unsigned ki = key[i], kp = key[p2];
            if ((ki > kp) == up) {
                key[i] = kp; key[p2] = ki;
                int ti = id[i]; id[i] = id[p2]; id[p2] = ti;
            }
            __syncthreads();
        }
    }
    g_order[t] = id[t];
    g_order[t + 1024] = id[t + 1024];
}

// ---------------- k1: fused per-pixel L2-normalize + transpose + fp16 cast --------
// One launch, both tensors. Read path: thread = (channel-row cr 0..31, float4
// pixel p4 0..7) -> 12 independent LDG.128 per thread.
#define PIX 32
__global__ void __launch_bounds__(256) k_norm_transpose(const float* __restrict__ teacher,
                                                        const float* __restrict__ student) {
    __shared__ float tile[CC][PIX + 1];
    __shared__ float ssum[32][PIX + 1];
    __shared__ float rinv[PIX];
    const int blocks_per_tensor = BB * HW / PIX;      // 4608
    int blk  = blockIdx.x;
    bool is_student = (blk >= blocks_per_tensor);
    if (is_student) blk -= blocks_per_tensor;
    const float* in = is_student ? student : teacher;
    __half* gout    = is_student ? g_sn : g_tn;

    int b    = blk / (HW / PIX);
    int pix0 = (blk % (HW / PIX)) * PIX;
    int t    = threadIdx.x;
    int p4   = t & 7;                        // float4 pixel index (0..7)
    int cr   = t >> 3;                       // channel row group (0..31)
    const float* src = in + (size_t)b * CC * HW + pix0;
    float a0 = 0.f, a1 = 0.f, a2 = 0.f, a3 = 0.f;
#pragma unroll
    for (int i = 0; i < CC / 32; i++) {      // 12 iters, LDG.128, fully coalesced
        int c = i * 32 + cr;
        float4 v = *(const float4*)(src + (size_t)c * HW + p4 * 4);
        tile[c][p4 * 4 + 0] = v.x;
        tile[c][p4 * 4 + 1] = v.y;
        tile[c][p4 * 4 + 2] = v.z;
        tile[c][p4 * 4 + 3] = v.w;
        a0 = fmaf(v.x, v.x, a0);
        a1 = fmaf(v.y, v.y, a1);
        a2 = fmaf(v.z, v.z, a2);
        a3 = fmaf(v.w, v.w, a3);
    }
    ssum[cr][p4 * 4 + 0] = a0;
    ssum[cr][p4 * 4 + 1] = a1;
    ssum[cr][p4 * 4 + 2] = a2;
    ssum[cr][p4 * 4 + 3] = a3;
    __syncthreads();
    if (t < PIX) {                           // one warp: reduce 32 partials/pixel
        float s = 0.0f;
#pragma unroll
        for (int r = 0; r < 32; r++) s += ssum[r][t];
        rinv[t] = 1.0f / fmaxf(sqrtf(s), 1e-12f);
    }
    __syncthreads();
    int lane = t & 31, w = t >> 5;           // 8 warps, 4 pixels each
    __half2* dst = (__half2*)(gout + ((size_t)b * HW + pix0) * CC);
#pragma unroll
    for (int j = 0; j < PIX / 8; j++) {      // 4 pixels per warp
        int pp = w * (PIX / 8) + j;
        float r = rinv[pp];
#pragma unroll
        for (int i2 = 0; i2 < CC / 64; i2++) {  // 6, 128B coalesced half2 stores
            int h2i = lane + 32 * i2;            // half2 index 0..191
            int c = 2 * h2i;
            dst[(size_t)pp * (CC / 2) + h2i] =
                __floats2half2_rn(tile[c][pp] * r, tile[c + 1][pp] * r);
        }
    }
}

// ---------------- distributed window sims (fp16, fp32 accumulate) ----------------
// Warp layout: lane = 8*g + l. Group g owns offsets o = g*13+j. Lane l covers
// channel-chunks {l+8i} (uint4 = 8 halves). Neighbor loads in 5+4+4 batches:
// peak live buffer 20 regs, targeting a 64-reg budget for 4 blocks/SM.
template <int NB>
__device__ __forceinline__ void sims_batch(const uint4* __restrict__ cp, int ci,
                                           __half2 c0, __half2 c1, __half2 c2, __half2 c3,
                                           int obase, int g, float* s) {
    uint4 n[NB];
#pragma unroll
    for (int j = 0; j < NB; j++)
        n[j] = cp[ci + c_doff[g * 13 + obase + j] * (CC / 8)];
#pragma unroll
    for (int j = 0; j < NB; j++) {
        __half2 a = __hmul2(c0, *(__half2*)&n[j].x);
        a = __hfma2(c1, *(__half2*)&n[j].y, a);
        a = __hfma2(c2, *(__half2*)&n[j].z, a);
        a = __hfma2(c3, *(__half2*)&n[j].w, a);
        float2 f = __half22float2(a);
        s[obase + j] += f.x + f.y;
    }
}

__device__ __forceinline__ void window_sims13(const __half* __restrict__ feat,
                                              int b, int y, int x,
                                              int g, int l, float s[13]) {
    const uint4* cp = ((const uint4*)(feat + (size_t)b * HW * CC))
                    + (size_t)(y * WW + x) * (CC / 8);
#pragma unroll
    for (int j = 0; j < 13; j++) s[j] = 0.0f;
#pragma unroll
    for (int i = 0; i < 6; i++) {
        int ci = l + 8 * i;
        uint4 cv = cp[ci];
        __half2 c0 = *(__half2*)&cv.x, c1 = *(__half2*)&cv.y;
        __half2 c2 = *(__half2*)&cv.z, c3 = *(__half2*)&cv.w;
        sims_batch<5>(cp, ci, c0, c1, c2, c3, 0, g, s);
        sims_batch<4>(cp, ci, c0, c1, c2, c3, 5, g, s);
        sims_batch<4>(cp, ci, c0, c1, c2, c3, 9, g, s);
    }
#pragma unroll
    for (int j = 0; j < 13; j++) {
        float v = s[j];
        v += __shfl_xor_sync(0xffffffffu, v, 1);
        v += __shfl_xor_sync(0xffffffffu, v, 2);
        v += __shfl_xor_sync(0xffffffffu, v, 4);
        s[j] = v * TAU_INV;
    }
}

// ---------------- k2: candidate sims (stored) + entropy, Morton-ordered ----------
__global__ void __launch_bounds__(256, 4) k_cand(const int* __restrict__ anchors) {
    int gw   = (blockIdx.x * blockDim.x + threadIdx.x) >> 5;
    int lane = threadIdx.x & 31;
    if (gw >= BB * CAND) return;
    int b = gw >> 11;                  // / CAND
    int m = g_order[gw & (CAND - 1)];  // Morton-sorted processing order
    int y = anchors[2 * m], x = anchors[2 * m + 1];
    int g = lane >> 3, l = lane & 7;
    bool lead = (l == 0);

    float s[13];
    window_sims13(g_tn, b, y, x, g, l, s);

    // store sims row by ORIGINAL id (group leaders)
    float* srow = g_sims + ((size_t)(b << 11) + m) * KK2;
    if (lead) {
#pragma unroll
        for (int j = 0; j < 13; j++) {
            int o = g * 13 + j;
            if (o < KK2) srow[o] = s[j];
        }
    }

    // distributed entropy of softmax(s)
    float mx = -1e30f;
#pragma unroll
    for (int j = 0; j < 13; j++) {
        int o = g * 13 + j;
        if (o < KK2) mx = fmaxf(mx, s[j]);
    }
#pragma unroll
    for (int off = 16; off; off >>= 1) mx = fmaxf(mx, __shfl_xor_sync(0xffffffffu, mx, off));

    float S = 0.0f;
#pragma unroll
    for (int j = 0; j < 13; j++) {
        int o = g * 13 + j;
        if (lead && o < KK2) S += __expf(s[j] - mx);
    }
#pragma unroll
    for (int off = 16; off; off >>= 1) S += __shfl_xor_sync(0xffffffffu, S, off);
    float rS = 1.0f / S;

    float tacc = 0.0f;
#pragma unroll
    for (int j = 0; j < 13; j++) {
        int o = g * 13 + j;
        if (lead && o < KK2) {
            float p = __expf(s[j] - mx) * rS;
            tacc += p * __logf(p + 1e-6f);
        }
    }
#pragma unroll
    for (int off = 16; off; off >>= 1) tacc += __shfl_xor_sync(0xffffffffu, tacc, off);

    if (lane == 0) g_ent[(b << 11) | m] = -tacc;
}

// ---------------- k3: exact top-512 per batch + Morton re-sort of selection ------
__global__ void __launch_bounds__(1024) k_topk(const int* __restrict__ anchors) {
    __shared__ float v[CAND];
    __shared__ int   idx[CAND];
    __shared__ unsigned mk[ANCH];
    __shared__ int      mi[ANCH];
    int b = blockIdx.x;
    int t = threadIdx.x;   // 1024
    v[t]          = g_ent[b * CAND + t];
    v[t + 1024]   = g_ent[b * CAND + t + 1024];
    idx[t]        = t;
    idx[t + 1024] = t + 1024;
    __syncthreads();
    for (int kk = 2; kk <= CAND; kk <<= 1) {
        for (int j = kk >> 1; j > 0; j >>= 1) {
            int i  = ((t & ~(j - 1)) << 1) | (t & (j - 1));
            int p2 = i | j;
            bool up = ((i & kk) == 0);
            float vi = v[i], vp = v[p2];
            if ((vi > vp) == up) {
                v[i] = vp; v[p2] = vi;
                int ti = idx[i]; idx[i] = idx[p2]; idx[p2] = ti;
            }
            __syncthreads();
        }
    }
    // first 512 = smallest entropies; re-sort them by Morton code for k_kl locality
    if (t < ANCH) {
        int id = idx[t];
        mi[t] = id;
        mk[t] = morton7(anchors[2 * id], anchors[2 * id + 1]);
    }
    __syncthreads();
    for (int kk = 2; kk <= ANCH; kk <<= 1) {
        for (int j = kk >> 1; j > 0; j >>= 1) {
            if (t < ANCH / 2) {
                int i  = ((t & ~(j - 1)) << 1) | (t & (j - 1));
                int p2 = i | j;
                bool up = ((i & kk) == 0);
                unsigned ki = mk[i], kp = mk[p2];
                if ((ki > kp) == up) {
                    mk[i] = kp; mk[p2] = ki;
                    int ti = mi[i]; mi[i] = mi[p2]; mi[p2] = ti;
                }
            }
            __syncthreads();
        }
    }
    if (t < ANCH) g_sel[b * ANCH + t] = mi[t];
}

// ---------------- k4: KL divergence over selected anchors (Morton-ordered) -------
__global__ void __launch_bounds__(256, 4) k_kl(const int* __restrict__ anchors) {
    int gw   = (blockIdx.x * blockDim.x + threadIdx.x) >> 5;
    int lane = threadIdx.x & 31;
    if (gw >= BB * ANCH) return;
    int b = gw >> 9;             // / ANCH
    int m = g_sel[gw];
    int y = anchors[2 * m], x = anchors[2 * m + 1];
    int g = lane >> 3, l = lane & 7;
    bool lead = (l == 0);

    float ss[13];
    window_sims13(g_sn, b, y, x, g, l, ss);

    const float* trow = g_sims + ((size_t)(b << 11) + m) * KK2;
    float st[13];
#pragma unroll
    for (int j = 0; j < 13; j++) {
        int o = g * 13 + j;
        st[j] = (o < KK2) ? trow[o] : -1e30f;   // group-broadcast loads
    }

    float mxs = -1e30f, mxt = -1e30f;
#pragma unroll
    for (int j = 0; j < 13; j++) {
        int o = g * 13 + j;
        if (o < KK2) mxs = fmaxf(mxs, ss[j]);
        mxt = fmaxf(mxt, st[j]);                // invalid slots are -1e30
    }
#pragma unroll
    for (int off = 16; off; off >>= 1) {
        mxs = fmaxf(mxs, __shfl_xor_sync(0xffffffffu, mxs, off));
        mxt = fmaxf(mxt, __shfl_xor_sync(0xffffffffu, mxt, off));
    }

    float Ss = 0.0f, St = 0.0f;
#pragma unroll
    for (int j = 0; j < 13; j++) {
        int o = g * 13 + j;
        if (lead && o < KK2) {
            Ss += __expf(ss[j] - mxs);
            St += __expf(st[j] - mxt);
        }
    }
#pragma unroll
    for (int off = 16; off; off >>= 1) {
        Ss += __shfl_xor_sync(0xffffffffu, Ss, off);
        St += __shfl_xor_sync(0xffffffffu, St, off);
    }
    float ls = __logf(Ss), lt = __logf(St);
    float rSt = 1.0f / St;

    float kacc = 0.0f;
#pragma unroll
    for (int j = 0; j < 13; j++) {
        int o = g * 13 + j;
        if (lead && o < KK2) {
            float dt = st[j] - mxt - lt;
            float ds = ss[j] - mxs - ls;
            kacc += __expf(st[j] - mxt) * (dt - ds);
        }
    }
#pragma unroll
    for (int off = 16; off; off >>= 1) kacc += __shfl_xor_sync(0xffffffffu, kacc, off);

    if (lane == 0) atomicAdd(&g_loss, kacc * rSt);
}

// ---------------- k5: finalize ----------------
__global__ void k_final(float* __restrict__ out) {
    out[0] = g_loss / (float)(BB * ANCH);
}

// ---------------- launch: kernel launches ONLY (graph-capture safe) ----------------
extern "C" void kernel_launch(void* const* d_in, const int* in_sizes, int n_in,
                              void* d_out, int out_size) {
    const float* student = (const float*)d_in[0];
    const float* teacher = (const float*)d_in[1];
    const int*   anchors = (const int*)d_in[2];
    float* out = (float*)d_out;

    k_sort<<<1, 1024>>>(anchors);                   // also zeroes g_loss

    int nt_blocks = 2 * BB * HW / PIX;              // 9216 (both tensors, one launch)
    k_norm_transpose<<<nt_blocks, 256>>>(teacher, student);

    int cand_blocks = BB * CAND / 8;                // 4096 blocks, 8 warps each
    k_cand<<<cand_blocks, 256>>>(anchors);

    k_topk<<<BB, 1024>>>(anchors);

    int kl_blocks = BB * ANCH / 8;                  // 1024 blocks
    k_kl<<<kl_blocks, 256>>>(anchors);

    k_final<<<1, 1>>>(out);
}

// round 14
// speedup vs baseline: 1.0645x; 1.0296x over previous
#include <cuda_runtime.h>
#include <cuda_fp16.h>
#include <math.h>

#define BB 16
#define CC 384
#define HH 96
#define WW 96
#define HW (HH*WW)
#define CAND 2048
#define ANCH 512
#define KK2 49
#define TAU_INV 10.0f

// ---------------- scratch (device globals; no allocation anywhere) ----------------
__device__ __half g_tn[(size_t)BB*HW*CC];     // teacher, normalized, channels-last, fp16
__device__ __half g_sn[(size_t)BB*HW*CC];     // student,  normalized, channels-last, fp16
__device__ float g_sims[(size_t)BB*CAND*KK2]; // teacher sims (already /TAU), by ORIGINAL id
__device__ float g_ent[BB*CAND];              // by ORIGINAL id
__device__ int   g_order[CAND];               // candidate ids, Morton-sorted
__device__ int   g_sel[BB*ANCH];              // selected ids, Morton-sorted per batch
__device__ float g_loss;

// pixel offsets dy*WW+dx, row-major 7x7, padded to 52 with 0 (center: L1-resident)
__constant__ int c_doff[52] = {
 -291,-290,-289,-288,-287,-286,-285,
 -195,-194,-193,-192,-191,-190,-189,
  -99, -98, -97, -96, -95, -94, -93,
   -3,  -2,  -1,   0,   1,   2,   3,
   93,  94,  95,  96,  97,  98,  99,
  189, 190, 191, 192, 193, 194, 195,
  285, 286, 287, 288, 289, 290, 291,
    0,   0,   0 };

__device__ __forceinline__ unsigned morton7(int y, int x) {
    unsigned m = 0;
#pragma unroll
    for (int i = 0; i < 7; i++)
        m |= (((unsigned)(y >> i) & 1u) << (2 * i + 1)) | (((unsigned)(x >> i) & 1u) << (2 * i));
    return m;
}

// ---------------- candidate Morton sort body (256 threads, 4 pairs/round) ---------
__device__ void sort_candidates(const int* __restrict__ anchors,
                                unsigned* key, int* id) {
    int t = threadIdx.x;                 // 256
    if (t == 0) g_loss = 0.0f;
#pragma unroll
    for (int h = 0; h < 8; h++) {
        int m = t + h * 256;
        key[m] = morton7(anchors[2 * m], anchors[2 * m + 1]);
        id[m]  = m;
    }
    __syncthreads();
    for (int kk = 2; kk <= CAND; kk <<= 1) {
        for (int j = kk >> 1; j > 0; j >>= 1) {
            int ii[4], pp[4]; unsigned av[4], bv[4]; int ai[4], bi[4];
#pragma unroll
            for (int q = 0; q < 4; q++) {
                int tt = t + q * 256;
                ii[q] = ((tt & ~(j - 1)) << 1) | (tt & (j - 1));
                pp[q] = ii[q] | j;
                av[q] = key[ii[q]]; bv[q] = key[pp[q]];
                ai[q] = id[ii[q]];  bi[q] = id[pp[q]];
            }
#pragma unroll
            for (int q = 0; q < 4; q++) {
                bool up = ((ii[q] & kk) == 0);
                if ((av[q] > bv[q]) == up) {
                    key[ii[q]] = bv[q]; key[pp[q]] = av[q];
                    id[ii[q]]  = bi[q]; id[pp[q]]  = ai[q];
                }
            }
            __syncthreads();
        }
    }
#pragma unroll
    for (int h = 0; h < 8; h++) g_order[t + h * 256] = id[t + h * 256];
}

// ---------------- k1: fused L2-normalize + transpose + fp16 cast (+ sort block) ---
// Grid = 2*4608 + 1. Last block Morton-sorts the candidates (reusing tile smem)
// while the others stream the two tensors. fp16 tile halves smem -> 6 blocks/SM.
#define PIX 32
#define TROW 42   // halves per tile row (84B stride: 4B-aligned, <=2-way LDS conflicts)
__global__ void __launch_bounds__(256) k_norm_transpose(const float* __restrict__ teacher,
                                                        const float* __restrict__ student,
                                                        const int* __restrict__ anchors) {
    __shared__ __align__(16) __half tile[CC * TROW];   // 32256 B
    __shared__ float ssum[32][PIX + 1];                // 4224 B
    __shared__ float rinv[PIX];
    const int bpt = BB * HW / PIX;                     // 4608
    int blk  = blockIdx.x;
    if (blk >= 2 * bpt) {                              // sort block
        unsigned* key = (unsigned*)tile;
        int* id = (int*)(key + CAND);
        sort_candidates(anchors, key, id);
        return;
    }
    bool is_student = (blk >= bpt);
    if (is_student) blk -= bpt;
    const float* in = is_student ? student : teacher;
    __half* gout    = is_student ? g_sn : g_tn;

    int b    = blk / (HW / PIX);
    int pix0 = (blk % (HW / PIX)) * PIX;
    int t    = threadIdx.x;
    int p4   = t & 7;                        // float4 pixel index (0..7)
    int cr   = t >> 3;                       // channel row group (0..31)
    const float* src = in + (size_t)b * CC * HW + pix0;
    float a0 = 0.f, a1 = 0.f, a2 = 0.f, a3 = 0.f;
#pragma unroll
    for (int i = 0; i < CC / 32; i++) {      // 12 iters, LDG.128, fully coalesced
        int c = i * 32 + cr;
        float4 v = *(const float4*)(src + (size_t)c * HW + p4 * 4);
        *(__half2*)&tile[c * TROW + p4 * 4]     = __floats2half2_rn(v.x, v.y);
        *(__half2*)&tile[c * TROW + p4 * 4 + 2] = __floats2half2_rn(v.z, v.w);
        a0 = fmaf(v.x, v.x, a0);
        a1 = fmaf(v.y, v.y, a1);
        a2 = fmaf(v.z, v.z, a2);
        a3 = fmaf(v.w, v.w, a3);
    }
    ssum[cr][p4 * 4 + 0] = a0;
    ssum[cr][p4 * 4 + 1] = a1;
    ssum[cr][p4 * 4 + 2] = a2;
    ssum[cr][p4 * 4 + 3] = a3;
    __syncthreads();
    if (t < PIX) {                           // one warp: reduce 32 partials/pixel
        float s = 0.0f;
#pragma unroll
        for (int r = 0; r < 32; r++) s += ssum[r][t];
        rinv[t] = 1.0f / fmaxf(sqrtf(s), 1e-12f);
    }
    __syncthreads();
    int lane = t & 31, w = t >> 5;           // 8 warps, 4 pixels each
    __half2* dst = (__half2*)(gout + ((size_t)b * HW + pix0) * CC);
#pragma unroll
    for (int j = 0; j < PIX / 8; j++) {      // 4 pixels per warp
        int pp = w * (PIX / 8) + j;
        float r = rinv[pp];
#pragma unroll
        for (int i2 = 0; i2 < CC / 64; i2++) {  // 6, 128B coalesced half2 stores
            int h2i = lane + 32 * i2;            // half2 index 0..191
            int c = 2 * h2i;
            float va = __half2float(tile[c * TROW + pp]);
            float vb = __half2float(tile[(c + 1) * TROW + pp]);
            dst[(size_t)pp * (CC / 2) + h2i] = __floats2half2_rn(va * r, vb * r);
        }
    }
}

// ---------------- distributed window sims (fp16, fp32 accumulate) ----------------
// Warp layout: lane = 8*g + l. Group g owns offsets o = g*13+j. Lane l covers
// channel-chunks {l+8i} (uint4 = 8 halves). Neighbor loads in 5+4+4 batches:
// peak live buffer 20 regs, 64-reg budget for 4 blocks/SM.
template <int NB>
__device__ __forceinline__ void sims_batch(const uint4* __restrict__ cp, int ci,
                                           __half2 c0, __half2 c1, __half2 c2, __half2 c3,
                                           int obase, int g, float* s) {
    uint4 n[NB];
#pragma unroll
    for (int j = 0; j < NB; j++)
        n[j] = cp[ci + c_doff[g * 13 + obase + j] * (CC / 8)];
#pragma unroll
    for (int j = 0; j < NB; j++) {
        __half2 a = __hmul2(c0, *(__half2*)&n[j].x);
        a = __hfma2(c1, *(__half2*)&n[j].y, a);
        a = __hfma2(c2, *(__half2*)&n[j].z, a);
        a = __hfma2(c3, *(__half2*)&n[j].w, a);
        float2 f = __half22float2(a);
        s[obase + j] += f.x + f.y;
    }
}

__device__ __forceinline__ void window_sims13(const __half* __restrict__ feat,
                                              int b, int y, int x,
                                              int g, int l, float s[13]) {
    const uint4* cp = ((const uint4*)(feat + (size_t)b * HW * CC))
                    + (size_t)(y * WW + x) * (CC / 8);
#pragma unroll
    for (int j = 0; j < 13; j++) s[j] = 0.0f;
#pragma unroll
    for (int i = 0; i < 6; i++) {
        int ci = l + 8 * i;
        uint4 cv = cp[ci];
        __half2 c0 = *(__half2*)&cv.x, c1 = *(__half2*)&cv.y;
        __half2 c2 = *(__half2*)&cv.z, c3 = *(__half2*)&cv.w;
        sims_batch<5>(cp, ci, c0, c1, c2, c3, 0, g, s);
        sims_batch<4>(cp, ci, c0, c1, c2, c3, 5, g, s);
        sims_batch<4>(cp, ci, c0, c1, c2, c3, 9, g, s);
    }
#pragma unroll
    for (int j = 0; j < 13; j++) {
        float v = s[j];
        v += __shfl_xor_sync(0xffffffffu, v, 1);
        v += __shfl_xor_sync(0xffffffffu, v, 2);
        v += __shfl_xor_sync(0xffffffffu, v, 4);
        s[j] = v * TAU_INV;
    }
}

// ---------------- k2: candidate sims (stored) + entropy, Morton-ordered ----------
__global__ void __launch_bounds__(256, 4) k_cand(const int* __restrict__ anchors) {
    int gw   = (blockIdx.x * blockDim.x + threadIdx.x) >> 5;
    int lane = threadIdx.x & 31;
    if (gw >= BB * CAND) return;
    int b = gw >> 11;                  // / CAND
    int m = g_order[gw & (CAND - 1)];  // Morton-sorted processing order
    int y = anchors[2 * m], x = anchors[2 * m + 1];
    int g = lane >> 3, l = lane & 7;
    bool lead = (l == 0);

    float s[13];
    window_sims13(g_tn, b, y, x, g, l, s);

    float* srow = g_sims + ((size_t)(b << 11) + m) * KK2;
    if (lead) {
#pragma unroll
        for (int j = 0; j < 13; j++) {
            int o = g * 13 + j;
            if (o < KK2) srow[o] = s[j];
        }
    }

    float mx = -1e30f;
#pragma unroll
    for (int j = 0; j < 13; j++) {
        int o = g * 13 + j;
        if (o < KK2) mx = fmaxf(mx, s[j]);
    }
#pragma unroll
    for (int off = 16; off; off >>= 1) mx = fmaxf(mx, __shfl_xor_sync(0xffffffffu, mx, off));

    float S = 0.0f;
#pragma unroll
    for (int j = 0; j < 13; j++) {
        int o = g * 13 + j;
        if (lead && o < KK2) S += __expf(s[j] - mx);
    }
#pragma unroll
    for (int off = 16; off; off >>= 1) S += __shfl_xor_sync(0xffffffffu, S, off);
    float rS = 1.0f / S;

    float tacc = 0.0f;
#pragma unroll
    for (int j = 0; j < 13; j++) {
        int o = g * 13 + j;
        if (lead && o < KK2) {
            float p = __expf(s[j] - mx) * rS;
            tacc += p * __logf(p + 1e-6f);
        }
    }
#pragma unroll
    for (int off = 16; off; off >>= 1) tacc += __shfl_xor_sync(0xffffffffu, tacc, off);

    if (lane == 0) g_ent[(b << 11) | m] = -tacc;
}

// ---------------- k3: top-512 per batch (256 thr, 4 pairs/round) + Morton re-sort -
__global__ void __launch_bounds__(256) k_topk(const int* __restrict__ anchors) {
    __shared__ float v[CAND];
    __shared__ int   idx[CAND];
    __shared__ unsigned mk[ANCH];
    __shared__ int      mi[ANCH];
    int b = blockIdx.x;
    int t = threadIdx.x;   // 256
#pragma unroll
    for (int h = 0; h < 8; h++) {
        int m = t + h * 256;
        v[m]   = g_ent[b * CAND + m];
        idx[m] = m;
    }
    __syncthreads();
    for (int kk = 2; kk <= CAND; kk <<= 1) {
        for (int j = kk >> 1; j > 0; j >>= 1) {
            int ii[4], pp[4]; float av[4], bv[4]; int ai[4], bi[4];
#pragma unroll
            for (int q = 0; q < 4; q++) {
                int tt = t + q * 256;
                ii[q] = ((tt & ~(j - 1)) << 1) | (tt & (j - 1));
                pp[q] = ii[q] | j;
                av[q] = v[ii[q]]; bv[q] = v[pp[q]];
                ai[q] = idx[ii[q]]; bi[q] = idx[pp[q]];
            }
#pragma unroll
            for (int q = 0; q < 4; q++) {
                bool up = ((ii[q] & kk) == 0);
                if ((av[q] > bv[q]) == up) {
                    v[ii[q]] = bv[q]; v[pp[q]] = av[q];
                    idx[ii[q]] = bi[q]; idx[pp[q]] = ai[q];
                }
            }
            __syncthreads();
        }
    }
    // first 512 = smallest entropies; re-sort them by Morton code for k_kl locality
#pragma unroll
    for (int h = 0; h < 2; h++) {
        int m = t + h * 256;
        int id = idx[m];
        mi[m] = id;
        mk[m] = morton7(anchors[2 * id], anchors[2 * id + 1]);
    }
    __syncthreads();
    for (int kk = 2; kk <= ANCH; kk <<= 1) {
        for (int j = kk >> 1; j > 0; j >>= 1) {
            int i  = ((t & ~(j - 1)) << 1) | (t & (j - 1));
            int p2 = i | j;
            bool up = ((i & kk) == 0);
            unsigned ki = mk[i], kp = mk[p2];
            if ((ki > kp) == up) {
                mk[i] = kp; mk[p2] = ki;
                int ti = mi[i]; mi[i] = mi[p2]; mi[p2] = ti;
            }
            __syncthreads();
        }
    }
#pragma unroll
    for (int h = 0; h < 2; h++) {
        int m = t + h * 256;
        g_sel[b * ANCH + m] = mi[m];
    }
}

// ---------------- k4: KL divergence over selected anchors (Morton-ordered) -------
__global__ void __launch_bounds__(256, 4) k_kl(const int* __restrict__ anchors) {
    int gw   = (blockIdx.x * blockDim.x + threadIdx.x) >> 5;
    int lane = threadIdx.x & 31;
    if (gw >= BB * ANCH) return;
    int b = gw >> 9;             // / ANCH
    int m = g_sel[gw];
    int y = anchors[2 * m], x = anchors[2 * m + 1];
    int g = lane >> 3, l = lane & 7;
    bool lead = (l == 0);

    float ss[13];
    window_sims13(g_sn, b, y, x, g, l, ss);

    const float* trow = g_sims + ((size_t)(b << 11) + m) * KK2;
    float st[13];
#pragma unroll
    for (int j = 0; j < 13; j++) {
        int o = g * 13 + j;
        st[j] = (o < KK2) ? trow[o] : -1e30f;   // group-broadcast loads
    }

    float mxs = -1e30f, mxt = -1e30f;
#pragma unroll
    for (int j = 0; j < 13; j++) {
        int o = g * 13 + j;
        if (o < KK2) mxs = fmaxf(mxs, ss[j]);
        mxt = fmaxf(mxt, st[j]);                // invalid slots are -1e30
    }
#pragma unroll
    for (int off = 16; off; off >>= 1) {
        mxs = fmaxf(mxs, __shfl_xor_sync(0xffffffffu, mxs, off));
        mxt = fmaxf(mxt, __shfl_xor_sync(0xffffffffu, mxt, off));
    }

    float Ss = 0.0f, St = 0.0f;
#pragma unroll
    for (int j = 0; j < 13; j++) {
        int o = g * 13 + j;
        if (lead && o < KK2) {
            Ss += __expf(ss[j] - mxs);
            St += __expf(st[j] - mxt);
        }
    }
#pragma unroll
    for (int off = 16; off; off >>= 1) {
        Ss += __shfl_xor_sync(0xffffffffu, Ss, off);
        St += __shfl_xor_sync(0xffffffffu, St, off);
    }
    float ls = __logf(Ss), lt = __logf(St);
    float rSt = 1.0f / St;

    float kacc = 0.0f;
#pragma unroll
    for (int j = 0; j < 13; j++) {
        int o = g * 13 + j;
        if (lead && o < KK2) {
            float dt = st[j] - mxt - lt;
            float ds = ss[j] - mxs - ls;
            kacc += __expf(st[j] - mxt) * (dt - ds);
        }
    }
#pragma unroll
    for (int off = 16; off; off >>= 1) kacc += __shfl_xor_sync(0xffffffffu, kacc, off);

    if (lane == 0) atomicAdd(&g_loss, kacc * rSt);
}

// ---------------- k5: finalize ----------------
__global__ void k_final(float* __restrict__ out) {
    out[0] = g_loss / (float)(BB * ANCH);
}

// ---------------- launch: kernel launches ONLY (graph-capture safe) ----------------
extern "C" void kernel_launch(void* const* d_in, const int* in_sizes, int n_in,
                              void* d_out, int out_size) {
    const float* student = (const float*)d_in[0];
    const float* teacher = (const float*)d_in[1];
    const int*   anchors = (const int*)d_in[2];
    float* out = (float*)d_out;

    int nt_blocks = 2 * BB * HW / PIX + 1;          // 9217: both tensors + sort block
    k_norm_transpose<<<nt_blocks, 256>>>(teacher, student, anchors);

    int cand_blocks = BB * CAND / 8;                // 4096 blocks, 8 warps each
    k_cand<<<cand_blocks, 256>>>(anchors);

    k_topk<<<BB, 256>>>(anchors);

    int kl_blocks = BB * ANCH / 8;                  // 1024 blocks
    k_kl<<<kl_blocks, 256>>>(anchors);

    k_final<<<1, 1>>>(out);
}